// round 17
// baseline (speedup 1.0000x reference)
#include <cuda_runtime.h>
#include <cuda_bf16.h>
#include <math.h>
#include <stdint.h>

// ---------------------------------------------------------------------------
// SupConLossWithPrototype, symmetric-fold edition.
// Compact row layout: [Fn (Nn) | zero pad | Fb (M-Nn) | zero pad] = 65*128 rows.
// Novel blocks compute only upper-triangle tiles; exp values are reduced both
// along rows (E_i) and columns (E_j) of each off-diagonal tile. Base blocks
// compute full rows. sumS via g = sum of novel rows as proto row 100.
// ---------------------------------------------------------------------------

#define MAXM 8192
#define NCHUNK 9
#define NBLK 65
#define STRIDE (NBLK * 128)              /* 8320 compact rows */
#define LOG2E5 7.2134752044448170f

__device__ __align__(16) __nv_bfloat16 d_F[(size_t)STRIDE * 128];
__device__ __align__(16) __nv_bfloat16 d_Bp[128 * 128];  // protos + g row 100
__device__ int    d_labC[STRIDE];
__device__ float  d_ds[STRIDE];
__device__ int    d_cnt[128];
__device__ int    d_Nn;
__device__ float  d_gpart[128 * 128];
__device__ float  d_Erow[(size_t)NCHUNK * STRIDE];
__device__ float  d_Ecol[(size_t)64 * STRIDE];
__device__ float4 d_P3[STRIDE];          // (psum, pexp, bipi, dg_raw)
__device__ float  d_blockloss[NBLK];
__device__ int    d_ctrA = 0;
__device__ int    d_ctrB = 0;
__device__ int    d_rowctr[NBLK];
__device__ int    d_ctrF = 0;

// ------------------------------ helpers ------------------------------------

__device__ __forceinline__ uint32_t s2u(const void* p) {
    uint32_t a;
    asm("{ .reg .u64 t; cvta.to.shared.u64 t, %1; cvt.u32.u64 %0, t; }"
        : "=r"(a) : "l"(p));
    return a;
}

__device__ __forceinline__ void cp16(uint32_t s, const void* g) {
    asm volatile("cp.async.cg.shared.global [%0], [%1], 16;" :: "r"(s), "l"(g));
}
#define CP_COMMIT() asm volatile("cp.async.commit_group;" ::: "memory")

__device__ __forceinline__ void ldsm4(uint32_t (&r)[4], uint32_t addr) {
    asm volatile("ldmatrix.sync.aligned.m8n8.x4.shared.b16 {%0,%1,%2,%3}, [%4];"
                 : "=r"(r[0]), "=r"(r[1]), "=r"(r[2]), "=r"(r[3]) : "r"(addr));
}

__device__ __forceinline__ void mma16816(float (&d)[4], const uint32_t (&a)[4],
                                         uint32_t b0, uint32_t b1) {
    asm volatile(
        "mma.sync.aligned.m16n8k16.row.col.f32.bf16.bf16.f32 "
        "{%0,%1,%2,%3}, {%4,%5,%6,%7}, {%8,%9}, {%0,%1,%2,%3};"
        : "+f"(d[0]), "+f"(d[1]), "+f"(d[2]), "+f"(d[3])
        : "r"(a[0]), "r"(a[1]), "r"(a[2]), "r"(a[3]), "r"(b0), "r"(b1));
}

__device__ __forceinline__ uint32_t swz(uint32_t base, int row, int kchunk) {
    return base + row * 256 + (((uint32_t)(kchunk ^ (row & 7))) << 4);
}
__device__ __forceinline__ uint32_t rowbase_addr(uint32_t base, int row) {
    return base + row * 256 + (((uint32_t)(row & 7)) << 4);
}

__device__ __forceinline__ float ex2f(float t) {
    float r;
    asm("ex2.approx.f32 %0, %1;" : "=f"(r) : "f"(t));
    return r;
}

__device__ __forceinline__ float fexp(float x) {
    float t = x * 1.4426950408889634f;
    float z = t + 12582912.0f;
    int   ki = __float_as_int(z) - 0x4B400000;
    float r = t - (z - 12582912.0f);
    float p =      1.5403530393381610e-4f;
    p = fmaf(p, r, 1.3333558146428443e-3f);
    p = fmaf(p, r, 9.6181291076284772e-3f);
    p = fmaf(p, r, 5.5504108664821580e-2f);
    p = fmaf(p, r, 2.4022650695910072e-1f);
    p = fmaf(p, r, 6.9314718055994531e-1f);
    p = fmaf(p, r, 1.0f);
    return __int_as_float(__float_as_int(p) + (ki << 23));
}

// ------------------- prep: flags + proto cvt + compact ---------------------
// 128 blocks x 256 threads (co-resident -> grid spin safe), 64 rows each.
// Compacts novel rows to [0,Nn), base rows to [Npad, Npad+Mb). Last exiter
// reduces g -> bf16 proto row 100, zero-pads the gaps, resets counters.

__global__ void prep_kernel(const float* __restrict__ F,
                            const int* __restrict__ labels,
                            const int* __restrict__ plab,
                            const float* __restrict__ protos,
                            int M, int B) {
    __shared__ int sPL[128];
    __shared__ int sLabS[64];
    __shared__ int sDest[64];
    __shared__ int sW[2];
    __shared__ int sBase, sNn;
    __shared__ int sLast;
    __shared__ float sg[16][128];
    __shared__ float sgv[128];
    int tid = threadIdx.x, lane = tid & 31, w = tid >> 5;
    int blk = blockIdx.x, nblk = gridDim.x;
    int r0 = blk * 64;

    if (tid < B) sPL[tid] = plab[tid];
    __syncthreads();

    int f = 0, lanePre = 0;
    if (tid < 64) {
        int lab = labels[r0 + tid];
        sLabS[tid] = lab;
        int hit = 0;
        #pragma unroll 4
        for (int b = 0; b < B; ++b) hit |= (lab == sPL[b]);
        f = hit ^ 1;
        unsigned bal = __ballot_sync(0xffffffffu, f);
        lanePre = __popc(bal & ((1u << lane) - 1u));
        if (lane == 0) sW[w] = __popc(bal);
    }
    __syncthreads();
    if (tid == 0) d_cnt[blk] = sW[0] + sW[1];

    if (blk == 0) {                      // protos -> bf16 tile rows 0..127
        for (int idx = tid; idx < 128 * 16; idx += 256) {
            int row = idx >> 4, kc = idx & 15;
            union { __nv_bfloat16 h[8]; uint4 u; } ph;
            if (row < B) {
                #pragma unroll
                for (int q = 0; q < 8; ++q)
                    ph.h[q] = __float2bfloat16(protos[row * 128 + kc * 8 + q]);
            } else {
                ph.u = make_uint4(0, 0, 0, 0);
            }
            ((uint4*)d_Bp)[row * 16 + kc] = ph.u;
        }
    }

    __threadfence();
    __syncthreads();
    if (tid == 0) {
        atomicAdd(&d_ctrA, 1);
        while (atomicAdd(&d_ctrA, 0) < nblk) { }
    }
    __syncthreads();
    __threadfence();

    // Nn (warp 0) and prefix base before blk (warp 1).
    if (w == 0) {
        int v = 0;
        #pragma unroll
        for (int q = 0; q < 4; ++q) v += __ldcg(&d_cnt[lane + q * 32]);
        #pragma unroll
        for (int off = 16; off; off >>= 1)
            v += __shfl_xor_sync(0xffffffffu, v, off);
        if (lane == 0) { sNn = v; if (blk == 0) d_Nn = v; }
    }
    if (w == 1) {
        int v = 0;
        #pragma unroll
        for (int q = 0; q < 4; ++q) {
            int idx = lane + q * 32;
            if (idx < blk) v += __ldcg(&d_cnt[idx]);
        }
        #pragma unroll
        for (int off = 16; off; off >>= 1)
            v += __shfl_xor_sync(0xffffffffu, v, off);
        if (lane == 0) sBase = v;
    }
    __syncthreads();
    int Nn = sNn;
    int Npad = (Nn + 127) & ~127;
    if (tid < 64) {
        int nb = sBase + (w ? sW[0] : 0) + lanePre;   // novel rows before this row
        sDest[tid] = f ? nb : (Npad + (r0 + tid - nb));
    }
    __syncthreads();

    int kc = tid & 15;
    float gacc[8];
    #pragma unroll
    for (int q = 0; q < 8; ++q) gacc[q] = 0.f;

    #pragma unroll
    for (int sub = 0; sub < 4; ++sub) {
        int rl = sub * 16 + (tid >> 4);
        int row = r0 + rl;
        int dest = sDest[rl];
        float4 v0 = *(const float4*)(F + (size_t)row * 128 + kc * 8);
        float4 v1 = *(const float4*)(F + (size_t)row * 128 + kc * 8 + 4);
        float av[8] = {v0.x, v0.y, v0.z, v0.w, v1.x, v1.y, v1.z, v1.w};
        union { __nv_bfloat16 h[8]; uint4 u; } ph;
        float dsp = 0.f;
        #pragma unroll
        for (int q = 0; q < 8; ++q) {
            ph.h[q] = __float2bfloat16(av[q]);
            dsp = fmaf(av[q], av[q], dsp);
        }
        ((uint4*)d_F)[(size_t)dest * 16 + kc] = ph.u;
        if (dest < Nn) {
            #pragma unroll
            for (int q = 0; q < 8; ++q) gacc[q] += av[q];
        }
        dsp += __shfl_xor_sync(0xffffffffu, dsp, 1);
        dsp += __shfl_xor_sync(0xffffffffu, dsp, 2);
        dsp += __shfl_xor_sync(0xffffffffu, dsp, 4);
        dsp += __shfl_xor_sync(0xffffffffu, dsp, 8);
        if (kc == 0) { d_ds[dest] = dsp; d_labC[dest] = sLabS[rl]; }
    }
    #pragma unroll
    for (int q = 0; q < 8; ++q) sg[tid >> 4][kc * 8 + q] = gacc[q];
    __syncthreads();
    if (tid < 128) {
        float s = 0.f;
        #pragma unroll
        for (int q = 0; q < 16; ++q) s += sg[q][tid];
        d_gpart[blk * 128 + tid] = s;
    }

    __threadfence();
    __syncthreads();
    if (tid == 0) sLast = (atomicAdd(&d_ctrB, 1) == nblk - 1);
    __syncthreads();
    if (sLast) {
        if (tid < 128) {
            float tot = 0.f;
            #pragma unroll 8
            for (int b = 0; b < 128; ++b)
                tot += __ldcg(&d_gpart[b * 128 + tid]);
            sgv[tid] = tot;
        }
        __syncthreads();
        if (tid < 16) {                  // g -> bf16 proto row 100
            union { __nv_bfloat16 h[8]; uint4 u; } ph;
            #pragma unroll
            for (int q = 0; q < 8; ++q)
                ph.h[q] = __float2bfloat16(sgv[tid * 8 + q]);
            ((uint4*)d_Bp)[100 * 16 + tid] = ph.u;
        }
        // Zero pads: rows [Nn, Npad) and [Npad+Mb, STRIDE).
        int Mb = M - Nn;
        int p1 = Npad - Nn;
        int p2 = STRIDE - (Npad + Mb);
        for (int idx = tid; idx < (p1 + p2) * 16; idx += 256) {
            int rr = idx >> 4, c = idx & 15;
            int row = (rr < p1) ? (Nn + rr) : (Npad + Mb + (rr - p1));
            ((uint4*)d_F)[(size_t)row * 16 + c] = make_uint4(0, 0, 0, 0);
        }
        if (tid == 0) { d_ctrA = 0; d_ctrB = 0; }
    }
}

// ---------------------- main symmetric exp-sum kernel ----------------------
// Grid (NBLK=65, NCHUNK). CTA (rb, chunk): tiles c = c0, c0+NCHUNK, ... with
// c >= rb for novel blocks (upper triangle), full range for base blocks.
// Off-diagonal novel tiles also emit column-sum partials (slot rb, block c).
// chunk-0 CTAs run the proto+g tile. Per-block arrival counts trigger
// deterministic row-loss assembly; last assembly does the final reduce.

__global__ __launch_bounds__(256, 2) void mma_expsum_kernel(
        float* __restrict__ out, int M, int B) {
    extern __shared__ char dyn[];
    __shared__ int sLab[128];
    __shared__ float sColS[128];
    __shared__ float smr[128];
    __shared__ int sAsm[10];
    __shared__ int sNasm, sFinal;
    const uint32_t rawb = s2u(dyn);
    const uint32_t sbase = (rawb + 1023) & ~1023u;
    char* alg = dyn + (sbase - rawb);
    const uint32_t sA = sbase;
    const uint32_t sB[2] = {sbase + 32768, sbase + 65536};

    int tid = threadIdx.x;
    int lane = tid & 31, w = tid >> 5;
    int wr = w >> 2, wc = w & 3;
    int rb = blockIdx.x;
    int chunk = blockIdx.y;
    int Nn = d_Nn;
    int Npad = (Nn + 127) & ~127;
    int nNov = Npad >> 7;
    int Mb = M - Nn;
    int ntiles = nNov;
    bool isNov = (rb < nNov);
    int lo = isNov ? rb : 0;
    int c0 = chunk;
    if (lo > c0) c0 += ((lo - c0 + NCHUNK - 1) / NCHUNK) * NCHUNK;
    int nt = (c0 < ntiles) ? ((ntiles - c0 + NCHUNK - 1) / NCHUNK) : 0;

    // Prologue: A tile (compact rows rb*128..) + B(c0).
    {
        const char* ga = (const char*)d_F + (size_t)rb * 32768;
        #pragma unroll
        for (int it = 0; it < 8; ++it) {
            int c = it * 256 + tid;
            cp16(swz(sA, c >> 4, c & 15), ga + (size_t)c * 16);
        }
        if (nt > 0) {
            const char* gb = (const char*)d_F + (size_t)c0 * 32768;
            #pragma unroll
            for (int it = 0; it < 8; ++it) {
                int c = it * 256 + tid;
                cp16(swz(sB[0], c >> 4, c & 15), gb + (size_t)c * 16);
            }
        }
        CP_COMMIT();
    }

    int rl = lane & 15;
    uint32_t khx = (uint32_t)(lane >> 4) << 4;
    uint32_t RA[4], RB[2][2];
    #pragma unroll
    for (int mi = 0; mi < 4; ++mi)
        RA[mi] = rowbase_addr(sA, wr * 64 + mi * 16 + rl) ^ khx;
    #pragma unroll
    for (int pb = 0; pb < 2; ++pb)
        #pragma unroll
        for (int n2 = 0; n2 < 2; ++n2)
            RB[pb][n2] = rowbase_addr(sB[pb], wc * 32 + n2 * 16 + rl) ^ khx;

    // Row masks (for colsum: only rows < Nn contribute to column sums).
    float mLo[4], mHi[4];
    #pragma unroll
    for (int mi = 0; mi < 4; ++mi) {
        int rbase = rb * 128 + wr * 64 + mi * 16 + (lane >> 2);
        mLo[mi] = (rbase < Nn) ? 1.f : 0.f;
        mHi[mi] = (rbase + 8 < Nn) ? 1.f : 0.f;
    }

    float rs[8];
    #pragma unroll
    for (int q = 0; q < 8; ++q) rs[q] = 0.f;
    int cl[8];
    int ncol = 0;

    for (int k = 0; k < nt; ++k) {
        int c = c0 + k * NCHUNK;
        int p = k & 1;
        asm volatile("cp.async.wait_group 0;" ::: "memory");
        __syncthreads();

        if (k + 1 < nt) {
            const char* gb = (const char*)d_F + (size_t)(c + NCHUNK) * 32768;
            #pragma unroll
            for (int it = 0; it < 8; ++it) {
                int cc = it * 256 + tid;
                cp16(swz(sB[1 - p], cc >> 4, cc & 15), gb + (size_t)cc * 16);
            }
            CP_COMMIT();
        }

        float acc[4][4][4];
        #pragma unroll
        for (int mi = 0; mi < 4; ++mi)
            #pragma unroll
            for (int ni = 0; ni < 4; ++ni)
                #pragma unroll
                for (int q = 0; q < 4; ++q) acc[mi][ni][q] = 0.f;

        #pragma unroll
        for (int ks = 0; ks < 8; ++ks) {
            uint32_t ko = (uint32_t)ks << 5;
            uint32_t a[4][4], b[2][4];
            #pragma unroll
            for (int mi = 0; mi < 4; ++mi)
                ldsm4(a[mi], RA[mi] ^ ko);
            #pragma unroll
            for (int n2 = 0; n2 < 2; ++n2)
                ldsm4(b[n2], RB[p][n2] ^ ko);
            #pragma unroll
            for (int mi = 0; mi < 4; ++mi)
                #pragma unroll
                for (int ni = 0; ni < 4; ++ni) {
                    int n2 = ni >> 1, pr = ni & 1;
                    mma16816(acc[mi][ni], a[mi], b[n2][pr], b[n2][pr + 2]);
                }
        }

        bool doCol = isNov && (c > rb);
        float cs[8];
        #pragma unroll
        for (int q = 0; q < 8; ++q) cs[q] = 0.f;

        int cwarp = c * 128 + wc * 32;
        if (cwarp + 32 <= Nn) {
            #pragma unroll
            for (int mi = 0; mi < 4; ++mi)
                #pragma unroll
                for (int ni = 0; ni < 4; ++ni) {
                    float e0 = ex2f(acc[mi][ni][0] * LOG2E5);
                    float e1 = ex2f(acc[mi][ni][1] * LOG2E5);
                    float e2 = ex2f(acc[mi][ni][2] * LOG2E5);
                    float e3 = ex2f(acc[mi][ni][3] * LOG2E5);
                    rs[mi * 2 + 0] += e0 + e1;
                    rs[mi * 2 + 1] += e2 + e3;
                    if (doCol) {
                        cs[ni * 2 + 0] = fmaf(mLo[mi], e0,
                                         fmaf(mHi[mi], e2, cs[ni * 2 + 0]));
                        cs[ni * 2 + 1] = fmaf(mLo[mi], e1,
                                         fmaf(mHi[mi], e3, cs[ni * 2 + 1]));
                    }
                }
        } else {
            #pragma unroll
            for (int mi = 0; mi < 4; ++mi)
                #pragma unroll
                for (int ni = 0; ni < 4; ++ni) {
                    int cc0 = cwarp + ni * 8 + (lane & 3) * 2;
                    bool v0 = (cc0 < Nn), v1 = (cc0 + 1 < Nn);
                    float e0 = ex2f(v0 ? acc[mi][ni][0] * LOG2E5 : -1e30f);
                    float e1 = ex2f(v1 ? acc[mi][ni][1] * LOG2E5 : -1e30f);
                    float e2 = ex2f(v0 ? acc[mi][ni][2] * LOG2E5 : -1e30f);
                    float e3 = ex2f(v1 ? acc[mi][ni][3] * LOG2E5 : -1e30f);
                    rs[mi * 2 + 0] += e0 + e1;
                    rs[mi * 2 + 1] += e2 + e3;
                    if (doCol) {
                        cs[ni * 2 + 0] = fmaf(mLo[mi], e0,
                                         fmaf(mHi[mi], e2, cs[ni * 2 + 0]));
                        cs[ni * 2 + 1] = fmaf(mLo[mi], e1,
                                         fmaf(mHi[mi], e3, cs[ni * 2 + 1]));
                    }
                }
        }

        if (doCol) {                     // column sums -> d_Ecol[rb][c rows]
            #pragma unroll
            for (int q = 0; q < 8; ++q) {
                cs[q] += __shfl_xor_sync(0xffffffffu, cs[q], 4);
                cs[q] += __shfl_xor_sync(0xffffffffu, cs[q], 8);
                cs[q] += __shfl_xor_sync(0xffffffffu, cs[q], 16);
            }
            __syncthreads();
            if (wr == 0 && lane < 4) {
                #pragma unroll
                for (int ni = 0; ni < 4; ++ni) {
                    sColS[wc * 32 + ni * 8 + lane * 2 + 0] = cs[ni * 2 + 0];
                    sColS[wc * 32 + ni * 8 + lane * 2 + 1] = cs[ni * 2 + 1];
                }
            }
            __syncthreads();
            if (wr == 1 && lane < 4) {
                #pragma unroll
                for (int ni = 0; ni < 4; ++ni) {
                    int col0 = wc * 32 + ni * 8 + lane * 2;
                    d_Ecol[(size_t)rb * STRIDE + c * 128 + col0] =
                        sColS[col0] + cs[ni * 2 + 0];
                    d_Ecol[(size_t)rb * STRIDE + c * 128 + col0 + 1] =
                        sColS[col0 + 1] + cs[ni * 2 + 1];
                }
            }
            cl[ncol++] = c;
        }
    }

    // ----------------- proto + g tile (chunk-0 CTAs) -----------------------
    if (chunk == 0) {
        if (tid < 128) sLab[tid] = d_labC[rb * 128 + tid];
        __syncthreads();
        {
            const char* gp = (const char*)d_Bp;
            #pragma unroll
            for (int it = 0; it < 8; ++it) {
                int c = it * 256 + tid;
                cp16(swz(sB[0], c >> 4, c & 15), gp + (size_t)c * 16);
            }
            CP_COMMIT();
        }
        asm volatile("cp.async.wait_group 0;" ::: "memory");
        __syncthreads();

        float acc[4][4][4];
        #pragma unroll
        for (int mi = 0; mi < 4; ++mi)
            #pragma unroll
            for (int ni = 0; ni < 4; ++ni)
                #pragma unroll
                for (int q = 0; q < 4; ++q) acc[mi][ni][q] = 0.f;

        #pragma unroll
        for (int ks = 0; ks < 8; ++ks) {
            uint32_t ko = (uint32_t)ks << 5;
            uint32_t a[4][4], b[2][4];
            #pragma unroll
            for (int mi = 0; mi < 4; ++mi)
                ldsm4(a[mi], RA[mi] ^ ko);
            #pragma unroll
            for (int n2 = 0; n2 < 2; ++n2)
                ldsm4(b[n2], RB[0][n2] ^ ko);
            #pragma unroll
            for (int mi = 0; mi < 4; ++mi)
                #pragma unroll
                for (int ni = 0; ni < 4; ++ni) {
                    int n2 = ni >> 1, pr = ni & 1;
                    mma16816(acc[mi][ni], a[mi], b[n2][pr], b[n2][pr + 2]);
                }
        }

        float ps[8], pe[8], bi[8];
        #pragma unroll
        for (int q = 0; q < 8; ++q) { ps[q] = 0.f; pe[q] = 0.f; bi[q] = 0.f; }
        #pragma unroll
        for (int mi = 0; mi < 4; ++mi) {
            int labLo = sLab[wr * 64 + mi * 16 + (lane >> 2)];
            int labHi = sLab[wr * 64 + mi * 16 + 8 + (lane >> 2)];
            #pragma unroll
            for (int ni = 0; ni < 4; ++ni) {
                int b0 = wc * 32 + ni * 8 + (lane & 3) * 2;
                if (b0 < B) {
                    float P0 = acc[mi][ni][0] * 5.0f;
                    float P2 = acc[mi][ni][2] * 5.0f;
                    ps[mi * 2 + 0] += P0;
                    ps[mi * 2 + 1] += P2;
                    pe[mi * 2 + 0] += ex2f(acc[mi][ni][0] * LOG2E5);
                    pe[mi * 2 + 1] += ex2f(acc[mi][ni][2] * LOG2E5);
                    if (b0 == labLo) bi[mi * 2 + 0] += P0;
                    if (b0 == labHi) bi[mi * 2 + 1] += P2;
                }
                if (b0 + 1 < B) {
                    float P1 = acc[mi][ni][1] * 5.0f;
                    float P3 = acc[mi][ni][3] * 5.0f;
                    ps[mi * 2 + 0] += P1;
                    ps[mi * 2 + 1] += P3;
                    pe[mi * 2 + 0] += ex2f(acc[mi][ni][1] * LOG2E5);
                    pe[mi * 2 + 1] += ex2f(acc[mi][ni][3] * LOG2E5);
                    if (b0 + 1 == labLo) bi[mi * 2 + 0] += P1;
                    if (b0 + 1 == labHi) bi[mi * 2 + 1] += P3;
                }
            }
        }
        #pragma unroll
        for (int q = 0; q < 8; ++q) {
            ps[q] += __shfl_xor_sync(0xffffffffu, ps[q], 1);
            ps[q] += __shfl_xor_sync(0xffffffffu, ps[q], 2);
            pe[q] += __shfl_xor_sync(0xffffffffu, pe[q], 1);
            pe[q] += __shfl_xor_sync(0xffffffffu, pe[q], 2);
            bi[q] += __shfl_xor_sync(0xffffffffu, bi[q], 1);
            bi[q] += __shfl_xor_sync(0xffffffffu, bi[q], 2);
        }
        // dg: raw col-100 accumulators live in lanes with (lane&3)==2, wc==3.
        float dgLo[4], dgHi[4];
        #pragma unroll
        for (int mi = 0; mi < 4; ++mi) {
            float vLo = acc[mi][0][0], vHi = acc[mi][0][2];
            vLo = __shfl_sync(0xffffffffu, vLo, (lane & 28) | 2);
            vHi = __shfl_sync(0xffffffffu, vHi, (lane & 28) | 2);
            dgLo[mi] = (wc == 3) ? vLo : 0.f;
            dgHi[mi] = (wc == 3) ? vHi : 0.f;
        }
        __syncthreads();
        float* sc = (float*)(alg + 65536);
        if ((lane & 3) == 0) {
            int g = lane >> 2;
            #pragma unroll
            for (int mi = 0; mi < 4; ++mi)
                #pragma unroll
                for (int r8 = 0; r8 < 2; ++r8) {
                    int row = wr * 64 + mi * 16 + r8 * 8 + g;
                    int o = (row * 4 + wc) * 4;
                    sc[o + 0] = ps[mi * 2 + r8];
                    sc[o + 1] = pe[mi * 2 + r8];
                    sc[o + 2] = bi[mi * 2 + r8];
                    sc[o + 3] = r8 ? dgHi[mi] : dgLo[mi];
                }
        }
        __syncthreads();
        if (tid < 128) {
            float a = 0.f, b2 = 0.f, c2 = 0.f, dgv = 0.f;
            #pragma unroll
            for (int q = 0; q < 4; ++q) {
                int o = (tid * 4 + q) * 4;
                a   += sc[o + 0];
                b2  += sc[o + 1];
                c2  += sc[o + 2];
                dgv += sc[o + 3];
            }
            d_P3[rb * 128 + tid] = make_float4(a, b2, c2, dgv);
        }
    }

    // ---- row-sum partials -> d_Erow[chunk] -----------------------------
    #pragma unroll
    for (int q = 0; q < 8; ++q) {
        rs[q] += __shfl_xor_sync(0xffffffffu, rs[q], 1);
        rs[q] += __shfl_xor_sync(0xffffffffu, rs[q], 2);
    }
    __syncthreads();
    float* sred = (float*)alg;
    if ((lane & 3) == 0) {
        int g = lane >> 2;
        #pragma unroll
        for (int mi = 0; mi < 4; ++mi)
            #pragma unroll
            for (int r8 = 0; r8 < 2; ++r8) {
                int row = wr * 64 + mi * 16 + r8 * 8 + g;
                sred[row * 4 + wc] = rs[mi * 2 + r8];
            }
    }
    __syncthreads();
    if (tid < 128) {
        float se = sred[tid * 4] + sred[tid * 4 + 1] +
                   sred[tid * 4 + 2] + sred[tid * 4 + 3];
        d_Erow[(size_t)chunk * STRIDE + rb * 128 + tid] = se;
    }

    // ---- arrivals + deterministic assembly --------------------------------
    __threadfence();
    __syncthreads();
    if (tid == 0) {
        int na = 0;
        int old = atomicAdd(&d_rowctr[rb], 1);
        int tgt = NCHUNK + (isNov ? rb : 0);
        if (old == tgt - 1) sAsm[na++] = rb;
        for (int j = 0; j < ncol; ++j) {
            int c = cl[j];
            int o2 = atomicAdd(&d_rowctr[c], 1);
            if (o2 == NCHUNK + c - 1) sAsm[na++] = c;
        }
        sNasm = na;
    }
    __syncthreads();
    int nasm = sNasm;

    for (int a = 0; a < nasm; ++a) {
        int b = sAsm[a];
        float loss = 0.f;
        if (tid < 128) {
            int i = b * 128 + tid;
            bool novelRow = (i < Nn);
            bool valid = novelRow || (i >= Npad && i < Npad + Mb);
            if (valid) {
                float E = 0.f;
                #pragma unroll
                for (int s = 0; s < NCHUNK; ++s)
                    E += __ldcg(&d_Erow[(size_t)s * STRIDE + i]);
                if (b < nNov)
                    for (int r = 0; r < b; ++r)
                        E += __ldcg(&d_Ecol[(size_t)r * STRIDE + i]);
                float4 p3 = __ldcg(&d_P3[i]);
                if (novelRow) {
                    float ds = __ldcg(&d_ds[i]);
                    float Sii = ds * 5.0f;
                    float den = (E - fexp(Sii)) + p3.x;
                    int cnt = Nn - 1;
                    if (cnt > 0) {
                        float sumS = p3.w * 5.0f - Sii;
                        loss = -((sumS - logf(den) * (float)cnt) / (float)cnt);
                    }
                } else {
                    loss = -(p3.z - logf(E + p3.y));
                }
            }
        }
        __syncthreads();
        if (tid < 128) smr[tid] = loss;
        __syncthreads();
        for (int off = 64; off; off >>= 1) {
            if (tid < off) smr[tid] += smr[tid + off];
            __syncthreads();
        }
        if (tid == 0) { d_blockloss[b] = smr[0]; d_rowctr[b] = 0; }
        __syncthreads();
    }

    if (nasm > 0) {
        __threadfence();
        __syncthreads();
        if (tid == 0) {
            int tot = atomicAdd(&d_ctrF, nasm) + nasm;
            sFinal = (tot == NBLK);
        }
        __syncthreads();
        if (sFinal && tid == 0) {
            float s = 0.f;
            for (int b = 0; b < NBLK; ++b) s += __ldcg(&d_blockloss[b]);
            out[0] = s / (float)M;
            d_ctrF = 0;
        }
    }
}

// ------------------------------- launcher ----------------------------------

extern "C" void kernel_launch(void* const* d_in, const int* in_sizes, int n_in,
                              void* d_out, int out_size) {
    const float* F      = (const float*)d_in[0];
    const int*   labels = (const int*)d_in[1];
    const float* protos = (const float*)d_in[2];
    const int*   plab   = (const int*)d_in[3];
    int M = in_sizes[1];                  // 8192
    int B = in_sizes[3];                  // 100

    prep_kernel<<<M / 64, 256>>>(F, labels, plab, protos, M, B);

    size_t smemMain = 98304 + 1024;
    cudaFuncSetAttribute(mma_expsum_kernel,
                         cudaFuncAttributeMaxDynamicSharedMemorySize,
                         (int)smemMain);
    mma_expsum_kernel<<<dim3(NBLK, NCHUNK), 256, smemMain>>>(
        (float*)d_out, M, B);
}